// round 3
// baseline (speedup 1.0000x reference)
#include <cuda_runtime.h>

#define BB 4
#define NN 1024
#define INF 256
#define OUTF 256
#define NH 8
#define BN (BB*NN)

// ---------------- scratch (allocation-free) ----------------
__device__ float g_buf[BN*OUTF];   // g = h @ W  (4 MB)
__device__ float ELraw[BN*NH];     // raw el
__device__ float ERraw[BN*NH];     // raw er
__device__ float Lbuf[BN*16];      // [exp(el) x8, exp(.2el) x8]
__device__ float Rbuf[BN*16];      // [exp(er) x8, exp(.2er) x8]
__device__ float c_buf[BN*NH];     // 1/s[b,j,h]

// packed f32x2 helpers
__device__ __forceinline__ unsigned long long pack2(float lo, float hi) {
    unsigned long long r;
    asm("mov.b64 %0, {%1, %2};" : "=l"(r) : "f"(lo), "f"(hi));
    return r;
}
__device__ __forceinline__ void ffma2(unsigned long long& d, unsigned long long a,
                                      unsigned long long b) {
    asm("fma.rn.f32x2 %0, %1, %2, %0;" : "+l"(d) : "l"(a), "l"(b));
}
union U2 { unsigned long long u; float2 f; };

// ---------------------------------------------------------------------------
// K1: g = X @ W, 64x64 tile, 4x4 micro-tile, f32x2. Epilogue: each 64-col
// block owns heads 2cb,2cb+1 entirely -> reduce el/er in-block via shuffles.
// ---------------------------------------------------------------------------
__global__ __launch_bounds__(256) void k_gemm(const float* __restrict__ X,
                                              const float* __restrict__ W,
                                              const float* __restrict__ aw) {
    __shared__ __align__(16) float2 Xs2[16][64];
    __shared__ __align__(16) float  Ws [16][64];
    const int t = threadIdx.x;
    const int row0 = (blockIdx.x >> 2) * 64;
    const int cb   = (blockIdx.x & 3) * 64;
    const int tx = t & 15, ty = t >> 4;
    const int r0 = ty * 4, c0 = tx * 4;

    unsigned long long acc[4][2];
#pragma unroll
    for (int r = 0; r < 4; r++) { acc[r][0] = 0ull; acc[r][1] = 0ull; }

    const int lr = t >> 2, lk4 = (t & 3) * 4;
    const int wk = t >> 4, wc = (t & 15) * 4;

    for (int k0 = 0; k0 < INF; k0 += 16) {
        float4 xv = *reinterpret_cast<const float4*>(&X[(row0 + lr) * INF + k0 + lk4]);
        float4 wv = *reinterpret_cast<const float4*>(&W[(k0 + wk) * OUTF + cb + wc]);
        __syncthreads();
        Xs2[lk4 + 0][lr] = make_float2(xv.x, xv.x);
        Xs2[lk4 + 1][lr] = make_float2(xv.y, xv.y);
        Xs2[lk4 + 2][lr] = make_float2(xv.z, xv.z);
        Xs2[lk4 + 3][lr] = make_float2(xv.w, xv.w);
        *reinterpret_cast<float4*>(&Ws[wk][wc]) = wv;
        __syncthreads();
#pragma unroll
        for (int kk = 0; kk < 16; kk++) {
            const ulonglong2* xp = reinterpret_cast<const ulonglong2*>(&Xs2[kk][r0]);
            ulonglong2 xa = xp[0], xb = xp[1];
            ulonglong2 wv2 = *reinterpret_cast<const ulonglong2*>(&Ws[kk][c0]);
            ffma2(acc[0][0], xa.x, wv2.x); ffma2(acc[0][1], xa.x, wv2.y);
            ffma2(acc[1][0], xa.y, wv2.x); ffma2(acc[1][1], xa.y, wv2.y);
            ffma2(acc[2][0], xb.x, wv2.x); ffma2(acc[2][1], xb.x, wv2.y);
            ffma2(acc[3][0], xb.y, wv2.x); ffma2(acc[3][1], xb.y, wv2.y);
        }
    }

    // aw weights for this thread's 4 columns (within-head cols (tx&7)*4..+3)
    const float4* awp = reinterpret_cast<const float4*>(aw);
    float4 aL = awp[tx & 7];
    float4 aR = awp[8 + (tx & 7)];

#pragma unroll
    for (int r = 0; r < 4; r++) {
        U2 a, b; a.u = acc[r][0]; b.u = acc[r][1];
        float4 o = make_float4(a.f.x, a.f.y, b.f.x, b.f.y);
        *reinterpret_cast<float4*>(&g_buf[(row0 + r0 + r) * OUTF + cb + c0]) = o;

        float el = o.x*aL.x + o.y*aL.y + o.z*aL.z + o.w*aL.w;
        float er = o.x*aR.x + o.y*aR.y + o.z*aR.z + o.w*aR.w;
        el += __shfl_xor_sync(0xffffffffu, el, 1);
        el += __shfl_xor_sync(0xffffffffu, el, 2);
        el += __shfl_xor_sync(0xffffffffu, el, 4);
        er += __shfl_xor_sync(0xffffffffu, er, 1);
        er += __shfl_xor_sync(0xffffffffu, er, 2);
        er += __shfl_xor_sync(0xffffffffu, er, 4);
        if ((tx & 7) == 0) {
            int head = (cb >> 5) + (tx >> 3);
            int row = row0 + r0 + r;
            ELraw[row * NH + head] = el;
            ERraw[row * NH + head] = er;
        }
    }
}

// ---------------------------------------------------------------------------
// K_exp: Lbuf/Rbuf = {exp(x), exp(0.2x)} per (row, head). 131K MUFU total.
// ---------------------------------------------------------------------------
__global__ __launch_bounds__(256) void k_exp() {
    int idx = blockIdx.x * 256 + threadIdx.x;   // < BN*NH
    int row = idx >> 3, h = idx & 7;
    float el = ELraw[idx], er = ERraw[idx];
    Lbuf[row * 16 + h]     = __expf(el);
    Lbuf[row * 16 + 8 + h] = __expf(0.2f * el);
    Rbuf[row * 16 + h]     = __expf(er);
    Rbuf[row * 16 + 8 + h] = __expf(0.2f * er);
}

// ---------------------------------------------------------------------------
// K2: c[b,j,h] = 1 / sum_i adj[b,i,j]*wexp(i,j,h)   (no MUFU in N^2 loop)
// ---------------------------------------------------------------------------
__global__ __launch_bounds__(256) void k_c(const float* __restrict__ adj) {
    __shared__ float ssum[8][32][8];
    const int t = threadIdx.x;
    const int b = blockIdx.x >> 5;
    const int j0 = (blockIdx.x & 31) * 32;
    const int jl = t & 31, ig = t >> 5;

    const float4* rrow = reinterpret_cast<const float4*>(&Rbuf[(b * NN + j0 + jl) * 16]);
    float4 rp0 = rrow[0], rp1 = rrow[1], rn0 = rrow[2], rn1 = rrow[3];
    float EPr[8] = {rp0.x, rp0.y, rp0.z, rp0.w, rp1.x, rp1.y, rp1.z, rp1.w};
    float ENr[8] = {rn0.x, rn0.y, rn0.z, rn0.w, rn1.x, rn1.y, rn1.z, rn1.w};

    float acc[8];
#pragma unroll
    for (int h = 0; h < 8; h++) acc[h] = 0.f;

    const float* adjcol = adj + (size_t)b * NN * NN + j0 + jl;
    for (int i = ig; i < NN; i += 8) {
        float a = __ldg(adjcol + (size_t)i * NN);
        const float4* lr = reinterpret_cast<const float4*>(&Lbuf[(b * NN + i) * 16]);
        float4 lp0 = __ldg(&lr[0]), lp1 = __ldg(&lr[1]);
        float4 ln0 = __ldg(&lr[2]), ln1 = __ldg(&lr[3]);
        float EPl[8] = {lp0.x, lp0.y, lp0.z, lp0.w, lp1.x, lp1.y, lp1.z, lp1.w};
        float ENl[8] = {ln0.x, ln0.y, ln0.z, ln0.w, ln1.x, ln1.y, ln1.z, ln1.w};
#pragma unroll
        for (int h = 0; h < 8; h++) {
            float p = EPl[h] * EPr[h];
            float q = ENl[h] * ENr[h];
            float w = (p >= 1.0f) ? p : q;
            acc[h] = fmaf(a, w, acc[h]);
        }
    }
#pragma unroll
    for (int h = 0; h < 8; h++) ssum[ig][jl][h] = acc[h];
    __syncthreads();

    {
        int jl2 = t >> 3, h = t & 7;
        float s = 0.f;
#pragma unroll
        for (int g = 0; g < 8; g++) s += ssum[g][jl2][h];
        c_buf[(b * NN + j0 + jl2) * NH + h] = 1.0f / s;
    }
}

// ---------------------------------------------------------------------------
// K3: out[b,i,h,:] = sum_j adj*wexp*c[j,h] * g[b,j,h,:]
// Grid 128 = (b, 32-row i tile). 256 thr: warp=h, thread = 4 il x 8 d.
// Per jj: 3 LDS.128 -> 32 FMA (16 FFMA2): fma-pipe bound.
// ---------------------------------------------------------------------------
struct SmemAgg {
    float4 Gs4[32][64];      // g tile [jj][h*8 + d4]          32 KB
    float  Wgt[8][32][32];   // [h][jj][il]                    32 KB
    float  adj_s[32][33];    // padded                         4.2 KB
    float  Ltile[32][16];    // Lbuf rows of the i tile        2 KB
    float4 Rv[32][8];        // (Rp*c, Rn*c, c, 0) per (jj,h)  2 KB
};

__global__ __launch_bounds__(256) void k_agg(const float* __restrict__ adj,
                                             float* __restrict__ out) {
    extern __shared__ char smraw[];
    SmemAgg& sm = *reinterpret_cast<SmemAgg*>(smraw);
    const int t = threadIdx.x;
    const int b = blockIdx.x >> 5;
    const int i0 = (blockIdx.x & 31) * 32;

    // stage Ltile once
#pragma unroll
    for (int m = 0; m < 2; m++) {
        int idx = t + m * 256;
        int il = idx >> 4, c = idx & 15;
        sm.Ltile[il][c] = Lbuf[(b * NN + i0 + il) * 16 + c];
    }
    __syncthreads();

    // roles
    const int h  = t >> 5;             // warp = head (both phases)
    const int q  = (t >> 3) & 3;       // d-group: d = 8q..8q+7
    const int ig = t & 7;              // il-group: il = 4*ig..4*ig+3
    const int wil = t & 31;            // weight-compute: il = lane
    const float Lp = sm.Ltile[wil][h];
    const float Ln = sm.Ltile[wil][8 + h];

    unsigned long long acc2[4][4];
#pragma unroll
    for (int r = 0; r < 4; r++)
#pragma unroll
        for (int c = 0; c < 4; c++) acc2[r][c] = 0ull;

    const float4* g4 = reinterpret_cast<const float4*>(g_buf);

    for (int j0 = 0; j0 < NN; j0 += 32) {
        __syncthreads();   // protect smem from previous sweep

        // stage adj tile (32x32)
#pragma unroll
        for (int m = 0; m < 4; m++) {
            int idx = t + m * 256;
            int il = idx >> 5, jj = idx & 31;
            sm.adj_s[il][jj] = adj[(size_t)(b * NN + i0 + il) * NN + j0 + jj];
        }
        // stage g tile (32 x 256 floats)
#pragma unroll
        for (int m = 0; m < 8; m++) {
            int v = t + m * 256;
            int jj = v >> 6, c4 = v & 63;
            sm.Gs4[jj][c4] = g4[(size_t)(b * NN + j0 + jj) * 64 + c4];
        }
        // stage per-(jj,h) scalars
        {
            int jj = t >> 3, rh = t & 7;
            float cc = c_buf[(b * NN + j0 + jj) * NH + rh];
            float Rp = Rbuf[(b * NN + j0 + jj) * 16 + rh] * cc;
            float Rn = Rbuf[(b * NN + j0 + jj) * 16 + 8 + rh] * cc;
            sm.Rv[jj][rh] = make_float4(Rp, Rn, cc, 0.f);
        }
        __syncthreads();

        // weight tile: warp h, lane il, loop jj. STS rows contiguous.
#pragma unroll 4
        for (int jj = 0; jj < 32; jj++) {
            float4 rv = sm.Rv[jj][h];                  // broadcast
            float p  = Lp * rv.x;
            float qn = Ln * rv.y;
            float w  = (p >= rv.z) ? p : qn;           // Lp*Rp >= 1 <=> p >= c
            sm.Wgt[h][jj][wil] = sm.adj_s[wil][jj] * w;
        }
        __syncthreads();

        // FMA sweep: 4 il x 8 d per thread, 3 LDS.128 per jj
#pragma unroll 4
        for (int jj = 0; jj < 32; jj++) {
            const ulonglong2* gp =
                reinterpret_cast<const ulonglong2*>(&sm.Gs4[jj][h * 8 + 2 * q]);
            ulonglong2 ga = gp[0], gb = gp[1];         // d = 8q..8q+7
            float4 wv = *reinterpret_cast<const float4*>(&sm.Wgt[h][jj][4 * ig]);
            unsigned long long w0 = pack2(wv.x, wv.x);
            unsigned long long w1 = pack2(wv.y, wv.y);
            unsigned long long w2 = pack2(wv.z, wv.z);
            unsigned long long w3 = pack2(wv.w, wv.w);
            ffma2(acc2[0][0], w0, ga.x); ffma2(acc2[0][1], w0, ga.y);
            ffma2(acc2[0][2], w0, gb.x); ffma2(acc2[0][3], w0, gb.y);
            ffma2(acc2[1][0], w1, ga.x); ffma2(acc2[1][1], w1, ga.y);
            ffma2(acc2[1][2], w1, gb.x); ffma2(acc2[1][3], w1, gb.y);
            ffma2(acc2[2][0], w2, ga.x); ffma2(acc2[2][1], w2, ga.y);
            ffma2(acc2[2][2], w2, gb.x); ffma2(acc2[2][3], w2, gb.y);
            ffma2(acc2[3][0], w3, ga.x); ffma2(acc2[3][1], w3, ga.y);
            ffma2(acc2[3][2], w3, gb.x); ffma2(acc2[3][3], w3, gb.y);
        }
    }

    float4* out4 = reinterpret_cast<float4*>(out);
#pragma unroll
    for (int il = 0; il < 4; il++) {
        int i = i0 + 4 * ig + il;
        U2 a0, a1, a2, a3;
        a0.u = acc2[il][0]; a1.u = acc2[il][1];
        a2.u = acc2[il][2]; a3.u = acc2[il][3];
        size_t base = (size_t)(b * NN + i) * 64 + h * 8 + 2 * q;
        out4[base]     = make_float4(a0.f.x, a0.f.y, a1.f.x, a1.f.y);
        out4[base + 1] = make_float4(a2.f.x, a2.f.y, a3.f.x, a3.f.y);
    }
}

// ---------------------------------------------------------------------------
extern "C" void kernel_launch(void* const* d_in, const int* in_sizes, int n_in,
                              void* d_out, int out_size) {
    const float* h_in = (const float*)d_in[0];
    const float* adj  = (const float*)d_in[1];
    const float* W    = (const float*)d_in[2];
    const float* aw   = (const float*)d_in[3];
    float* out = (float*)d_out;

    static bool attr_set = false;
    if (!attr_set) {
        cudaFuncSetAttribute(k_agg, cudaFuncAttributeMaxDynamicSharedMemorySize,
                             (int)sizeof(SmemAgg));
        attr_set = true;
    }

    k_gemm<<<256, 256>>>(h_in, W, aw);
    k_exp<<<BN * NH / 256, 256>>>();
    k_c<<<(BB * NN) / 32, 256>>>(adj);
    k_agg<<<(BB * NN) / 32, 256, sizeof(SmemAgg)>>>(adj, out);
}